// round 11
// baseline (speedup 1.0000x reference)
#include <cuda_runtime.h>
#include <cuda_fp16.h>
#include <cstdint>

#define NB    16
#define CIN   512
#define COUT  512
#define STY   512
#define HW    4096
#define EPSV  1e-8f

#define XM_ELEMS (NB * 32 * HW * 16)
#define NTILES_TOTAL 1024
#define NCTA 148

// ---------------- device scratch ----------------
__device__ float g_s[NB * CIN];
__device__ float g_demod[NB * COUT];
__device__ float g_wsq[COUT * CIN];
__device__ __align__(16) __half g_xm[XM_ELEMS];          // x*s fp16, [n][c16][p][16]
__device__ __align__(16) __half g_wB[32 * 4 * 9 * 128 * 16]; // [c16][cotile][tap][co128][16ci]
__device__ __align__(16) __half g_zero[1024];            // 2 KB zeros

// ---------------- PTX helpers ----------------
__device__ __forceinline__ uint32_t smem_u32(const void* p) {
    uint32_t a;
    asm("{ .reg .u64 t; cvta.to.shared.u64 t, %1; cvt.u32.u64 %0, t; }" : "=r"(a) : "l"(p));
    return a;
}
#define MBAR_INIT(mb, c) asm volatile("mbarrier.init.shared.b64 [%0], %1;" :: "r"((uint32_t)(mb)), "r"((uint32_t)(c)) : "memory")
#define MBAR_ARRIVE(mb)  asm volatile("mbarrier.arrive.shared.b64 _, [%0];" :: "r"((uint32_t)(mb)) : "memory")
#define MBAR_EXPECT(mb, n) asm volatile("mbarrier.arrive.expect_tx.shared.b64 _, [%0], %1;" :: "r"((uint32_t)(mb)), "r"((uint32_t)(n)) : "memory")
#define FENCE_ASYNC()    asm volatile("fence.proxy.async.shared::cta;" ::: "memory")

#define MBAR_WAIT(mb, ph) do {                                                   \
    uint32_t _mb = (uint32_t)(mb); uint32_t _ph = (uint32_t)(ph); uint32_t _dn;  \
    asm volatile("{ .reg .pred p; mbarrier.try_wait.parity.acquire.cta.shared::cta.b64 p, [%1], %2; selp.b32 %0, 1, 0, p; }" \
        : "=r"(_dn) : "r"(_mb), "r"(_ph) : "memory");                            \
    if (!_dn) {                                                                  \
        asm volatile("{ .reg .pred P1;\n"                                        \
            "WL_%=: mbarrier.try_wait.parity.acquire.cta.shared::cta.b64 P1, [%0], %1, 0x989680;\n" \
            "@P1 bra.uni WD_%=;\n bra.uni WL_%=;\n WD_%=: }"                     \
            :: "r"(_mb), "r"(_ph) : "memory");                                   \
    }                                                                            \
} while (0)

#define BULK(dst, src, sz, mb) \
    asm volatile("cp.async.bulk.shared::cta.global.mbarrier::complete_tx::bytes [%0], [%1], %2, [%3];" \
        :: "r"((uint32_t)(dst)), "l"(src), "r"((uint32_t)(sz)), "r"((uint32_t)(mb)) : "memory")

#define LDSM4(r, a) \
    asm volatile("ldmatrix.sync.aligned.m8n8.x4.shared.b16 {%0,%1,%2,%3}, [%4];" \
        : "=r"((r)[0]), "=r"((r)[1]), "=r"((r)[2]), "=r"((r)[3]) : "r"(a))

__device__ __forceinline__ void mma_f16(float* c, const uint32_t* a, const uint32_t* b) {
    asm volatile("mma.sync.aligned.m16n8k16.row.col.f32.f16.f16.f32 "
        "{%0,%1,%2,%3}, {%4,%5,%6,%7}, {%8,%9}, {%0,%1,%2,%3};"
        : "+f"(c[0]), "+f"(c[1]), "+f"(c[2]), "+f"(c[3])
        : "r"(a[0]), "r"(a[1]), "r"(a[2]), "r"(a[3]), "r"(b[0]), "r"(b[1]));
}

// ---------------- prep kernels ----------------
__global__ void k_style(const float* __restrict__ style,
                        const float* __restrict__ style_w,
                        const float* __restrict__ style_b) {
    int n = blockIdx.x, ci = threadIdx.x;
    const float* srow = style + n * STY;
    const float* wrow = style_w + ci * STY;
    float acc = 0.f;
    #pragma unroll 8
    for (int j = 0; j < STY; j++) acc += srow[j] * wrow[j];
    g_s[n * CIN + ci] = acc + style_b[ci];
}

__global__ void k_wprep(const float* __restrict__ weight) {
    int id = blockIdx.x * 256 + threadIdx.x;
    int ci = id & 511, co = id >> 9;
    const float* wp = weight + (size_t)(co * CIN + ci) * 9;
    int c16 = ci >> 4, cil = ci & 15;
    int cotile = co >> 7, col = co & 127;
    float s = 0.f;
    #pragma unroll
    for (int tap = 0; tap < 9; tap++) {
        float v = wp[tap];
        s += v * v;
        g_wB[(((size_t)(c16 * 4 + cotile) * 9 + tap) * 128 + col) * 16 + cil] =
            __float2half_rn(v);
    }
    g_wsq[co * CIN + ci] = s;
}

__global__ void k_demod() {
    int co = blockIdx.x, n = blockIdx.y;
    __shared__ float red[128];
    float acc = 0.f;
    for (int ci = threadIdx.x; ci < CIN; ci += 128) {
        float s = g_s[n * CIN + ci];
        acc += g_wsq[co * CIN + ci] * s * s;
    }
    red[threadIdx.x] = acc;
    __syncthreads();
    for (int st = 64; st > 0; st >>= 1) {
        if (threadIdx.x < st) red[threadIdx.x] += red[threadIdx.x + st];
        __syncthreads();
    }
    if (threadIdx.x == 0) g_demod[n * COUT + co] = rsqrtf(red[0] + EPSV);
}

__global__ void k_xmod(const float* __restrict__ x) {
    int b   = blockIdx.x;
    int n   = b >> 9;
    int c16 = (b >> 4) & 31;
    int pb  = b & 15;
    int p   = pb * 256 + threadIdx.x;
    const float* sp = g_s + n * CIN + c16 * 16;
    const float* xp = x + (size_t)(n * CIN + c16 * 16) * HW + p;
    uint32_t hi[8];
    #pragma unroll
    for (int j = 0; j < 8; j++) {
        float v0 = xp[(size_t)(2 * j) * HW]     * sp[2 * j];
        float v1 = xp[(size_t)(2 * j + 1) * HW] * sp[2 * j + 1];
        __half2 hp = __halves2half2(__float2half_rn(v0), __float2half_rn(v1));
        hi[j] = *reinterpret_cast<uint32_t*>(&hp);
    }
    size_t ob = ((size_t)(n * 32 + c16) * HW + p) * 16;
    uint4* oh = reinterpret_cast<uint4*>(g_xm + ob);
    oh[0] = make_uint4(hi[0], hi[1], hi[2], hi[3]);
    oh[1] = make_uint4(hi[4], hi[5], hi[6], hi[7]);
}

// ---------------- main HMMA kernel (persistent, 4-stage ring) ----------------
#define NSTG      4
#define A_BYTES   12672
#define B_BYTES   36864
#define SSTRIDE   (A_BYTES + B_BYTES)            // 49536
#define SM_DATA   1024
#define SM_EPI    (SM_DATA + NSTG * SSTRIDE)     // 199168
#define SMEM_TOTAL (SM_EPI + 8 * 2048)           // 215552
#define EXPECT_B  (6 * 2048 + B_BYTES)           // 49152

__device__ __forceinline__ void issue_stage(uint32_t sb, int ls, int bx) {
    int tord = ls >> 5, c16 = ls & 31;
    int tile = bx + NCTA * tord;
    int n = tile >> 6, rem = tile & 63;
    int h0 = (rem >> 2) * 4;
    int cotile = rem & 3;
    int slot = ls & 3;
    uint32_t sa = sb + SM_DATA + slot * SSTRIDE;
    uint32_t mb = sb + slot * 8;
    MBAR_EXPECT(mb, EXPECT_B);
    const __half* xbase = g_xm + ((size_t)(n * 32 + c16) * HW) * 16;
    #pragma unroll
    for (int r = 0; r < 6; r++) {
        int hh = h0 - 1 + r;
        const __half* src = ((unsigned)hh < 64u) ? (xbase + (size_t)hh * 64 * 16)
                                                 : g_zero;
        BULK(sa + (r * 66 + 1) * 32, src, 2048, mb);
    }
    BULK(sa + A_BYTES, g_wB + (size_t)(c16 * 4 + cotile) * 18432, B_BYTES, mb);
}

#define LOADB(BH, addr)                                           \
    do {                                                          \
        uint32_t _bb = (addr);                                    \
        uint32_t _bq[4];                                          \
        LDSM4(_bq, _bb);          (BH)[0][0]=_bq[0]; (BH)[0][1]=_bq[1]; (BH)[1][0]=_bq[2]; (BH)[1][1]=_bq[3]; \
        LDSM4(_bq, _bb + 512);    (BH)[2][0]=_bq[0]; (BH)[2][1]=_bq[1]; (BH)[3][0]=_bq[2]; (BH)[3][1]=_bq[3]; \
        LDSM4(_bq, _bb + 1024);   (BH)[4][0]=_bq[0]; (BH)[4][1]=_bq[1]; (BH)[5][0]=_bq[2]; (BH)[5][1]=_bq[3]; \
        LDSM4(_bq, _bb + 1536);   (BH)[6][0]=_bq[0]; (BH)[6][1]=_bq[1]; (BH)[7][0]=_bq[2]; (BH)[7][1]=_bq[3]; \
    } while (0)

// One tap. _sl/_sa are the (runtime) slot index / smem base for this stage.
#define TAPB(lsv, tapv, TOFF, CUR, NXT, ISLAST)                                  \
    do {                                                                         \
        uint32_t _aa = _sa + aoff0 + (TOFF);                                     \
        uint32_t ah0[4], ah1[4], ah2[4], ah3[4];                                 \
        LDSM4(ah0, _aa);                                                         \
        LDSM4(ah1, _aa + 512);                                                   \
        LDSM4(ah2, _aa + 1024);                                                  \
        LDSM4(ah3, _aa + 1536);                                                  \
        if (ISLAST) { if (lane == 0) MBAR_ARRIVE(sb + 64 + _sl * 8); }           \
        _Pragma("unroll")                                                        \
        for (int bn = 0; bn < 8; bn++) mma_f16(acc[0][bn], ah0, CUR[bn]);        \
        _Pragma("unroll")                                                        \
        for (int bn = 0; bn < 8; bn++) mma_f16(acc[1][bn], ah1, CUR[bn]);        \
        if (!(ISLAST)) {                                                         \
            LOADB(NXT, _sa + A_BYTES + ((tapv) + 1) * 4096 + boff);              \
        } else if ((lsv) + 1 < nls) {                                            \
            int _ns = ((lsv) + 1) & 3;                                           \
            MBAR_WAIT(sb + _ns * 8, (((lsv) + 1) >> 2) & 1);                     \
            LOADB(NXT, sb + SM_DATA + _ns * SSTRIDE + A_BYTES + boff);           \
        }                                                                        \
        _Pragma("unroll")                                                        \
        for (int bn = 0; bn < 8; bn++) mma_f16(acc[2][bn], ah2, CUR[bn]);        \
        _Pragma("unroll")                                                        \
        for (int bn = 0; bn < 8; bn++) mma_f16(acc[3][bn], ah3, CUR[bn]);        \
        if ((ISLAST) && (lsv) + NSTG < nls) {                                    \
            if (wid == ((lsv) & 7) && lane == 0) {                               \
                MBAR_WAIT(sb + 64 + _sl * 8, ((lsv) >> 2) & 1);                  \
                issue_stage(sb, (lsv) + NSTG, bx);                               \
            }                                                                    \
        }                                                                        \
    } while (0)

#define STAGE(lsv, B0, B1)                                 \
    do {                                                   \
        int _sl = (lsv) & 3;                               \
        uint32_t _sa = sb + SM_DATA + _sl * SSTRIDE;       \
        TAPB(lsv, 0, -2144, B0, B1, 0);                    \
        TAPB(lsv, 1, -2112, B1, B0, 0);                    \
        TAPB(lsv, 2, -2080, B0, B1, 0);                    \
        TAPB(lsv, 3,   -32, B1, B0, 0);                    \
        TAPB(lsv, 4,     0, B0, B1, 0);                    \
        TAPB(lsv, 5,    32, B1, B0, 0);                    \
        TAPB(lsv, 6,  2080, B0, B1, 0);                    \
        TAPB(lsv, 7,  2112, B1, B0, 0);                    \
        TAPB(lsv, 8,  2144, B0, B1, 1);                    \
    } while (0)

__global__ void __launch_bounds__(256, 1)
k_main(const float* __restrict__ noise,
       const float* __restrict__ nw_p,
       float* __restrict__ out) {
    extern __shared__ __align__(1024) char smem[];
    uint32_t sb = smem_u32(smem);
    int t = threadIdx.x, wid = t >> 5, lane = t & 31;
    int wm = wid & 3, wn = wid >> 2;
    int bx = blockIdx.x;

    int ntiles = (NTILES_TOTAL - bx + NCTA - 1) / NCTA;
    int nls = ntiles * 32;

    if (t == 0) {
        #pragma unroll
        for (int s = 0; s < NSTG; s++) {
            MBAR_INIT(sb + s * 8, 1);
            MBAR_INIT(sb + 64 + s * 8, 8);
        }
    }
    // zero all A regions (halo columns stay zero; rows always bulk-filled)
    {
        uint32_t zb = sb + SM_DATA;
        for (int i = t * 16; i < A_BYTES; i += 4096) {
            #pragma unroll
            for (int s = 0; s < NSTG; s++)
                asm volatile("st.shared.v4.b32 [%0], {%1,%1,%1,%1};"
                    :: "r"(zb + s * SSTRIDE + i), "r"(0u) : "memory");
        }
    }
    __syncthreads();
    if (lane == 0 && wid < NSTG) {
        FENCE_ASYNC();
        issue_stage(sb, wid, bx);
    }

    float acc[4][8][4];
    #pragma unroll
    for (int a = 0; a < 4; a++)
        #pragma unroll
        for (int b = 0; b < 8; b++)
            #pragma unroll
            for (int c = 0; c < 4; c++) acc[a][b][c] = 0.f;

    int bg = lane >> 3, br = lane & 7;
    uint32_t boff = (uint32_t)(wn * 64 + (bg >> 1) * 8 + br) * 32
                  + (uint32_t)(bg & 1) * 16;
    uint32_t aoff0 = (uint32_t)((wm + 1) * 66 + (lane & 15) + 1) * 32
                   + (uint32_t)(lane >> 4) * 16;

    uint32_t bhA[8][2], bhB[8][2];
    float nw = nw_p[0];

    // prologue: stage 0 ready -> tap0 B frags
    MBAR_WAIT(sb + 0, 0);
    LOADB(bhA, sb + SM_DATA + A_BYTES + boff);

    int tile = bx;
    for (int tord = 0; tord < ntiles; tord++, tile += NCTA) {
        int lsbase = tord * 32;
        for (int cc = 0; cc < 32; cc += 2) {
            STAGE(lsbase + cc,     bhA, bhB);
            STAGE(lsbase + cc + 1, bhB, bhA);
        }

        // ---- warp-local epilogue (overlaps next tile's bulk loads) ----
        {
            int n   = tile >> 6;
            int rem = tile & 63;
            int p0  = (rem >> 2) * 256;
            int co0 = (rem & 3) * 128;

            int q = lane & 3, rr = lane >> 2;
            int pxbase = p0 + wm * 64 + q * 16;
            float nzs[16];
            #pragma unroll
            for (int j = 0; j < 16; j++) nzs[j] = nw * noise[n * HW + pxbase + j];

            float* wsm = reinterpret_cast<float*>(smem + SM_EPI + wid * 2048);
            const float* dmrow = g_demod + n * COUT;

            #pragma unroll
            for (int g = 0; g < 8; g++) {
                #pragma unroll
                for (int am = 0; am < 4; am++) {
                    int px = am * 16 + (lane >> 2);
                    int col = (lane & 3) * 2;
                    wsm[col * 64 + px]           = acc[am][g][0];
                    wsm[(col + 1) * 64 + px]     = acc[am][g][1];
                    wsm[col * 64 + px + 8]       = acc[am][g][2];
                    wsm[(col + 1) * 64 + px + 8] = acc[am][g][3];
                }
                __syncwarp();
                int co = co0 + wn * 64 + g * 8 + rr;
                float d = dmrow[co];
                float* op = out + ((size_t)(n * COUT + co)) * HW + pxbase;
                const float* srp = wsm + rr * 64 + q * 16;
                #pragma unroll
                for (int j4 = 0; j4 < 4; j4++) {
                    float4 v = *reinterpret_cast<const float4*>(srp + j4 * 4);
                    float r0 = v.x * d + nzs[j4 * 4 + 0];
                    float r1 = v.y * d + nzs[j4 * 4 + 1];
                    float r2 = v.z * d + nzs[j4 * 4 + 2];
                    float r3 = v.w * d + nzs[j4 * 4 + 3];
                    r0 = (r0 >= 0.f) ? r0 : 0.2f * r0;
                    r1 = (r1 >= 0.f) ? r1 : 0.2f * r1;
                    r2 = (r2 >= 0.f) ? r2 : 0.2f * r2;
                    r3 = (r3 >= 0.f) ? r3 : 0.2f * r3;
                    *reinterpret_cast<float4*>(op + j4 * 4) = make_float4(r0, r1, r2, r3);
                }
                __syncwarp();
            }
        }

        #pragma unroll
        for (int a = 0; a < 4; a++)
            #pragma unroll
            for (int b = 0; b < 8; b++)
                #pragma unroll
                for (int c = 0; c < 4; c++) acc[a][b][c] = 0.f;
    }
}

// ---------------------------------------------------------------------------
extern "C" void kernel_launch(void* const* d_in, const int* in_sizes, int n_in,
                              void* d_out, int out_size) {
    const float* x            = (const float*)d_in[0];
    const float* style        = (const float*)d_in[1];
    const float* noise        = (const float*)d_in[2];
    const float* weight       = (const float*)d_in[3];
    const float* style_w      = (const float*)d_in[4];
    const float* style_b      = (const float*)d_in[5];
    const float* noise_weight = (const float*)d_in[6];
    float* out = (float*)d_out;

    cudaFuncSetAttribute(k_main, cudaFuncAttributeMaxDynamicSharedMemorySize, SMEM_TOTAL);

    k_style<<<NB, CIN>>>(style, style_w, style_b);
    k_wprep<<<1024, 256>>>(weight);
    {
        dim3 g(COUT, NB);
        k_demod<<<g, 128>>>();
    }
    k_xmod<<<8192, 256>>>(x);
    k_main<<<NCTA, 256, SMEM_TOTAL>>>(noise, noise_weight, out);
}

// round 12
// speedup vs baseline: 1.0047x; 1.0047x over previous
#include <cuda_runtime.h>
#include <cuda_fp16.h>
#include <cstdint>

#define NB    16
#define CIN   512
#define COUT  512
#define STY   512
#define HW    4096
#define EPSV  1e-8f

#define XM_ELEMS (NB * 32 * HW * 16)
#define NTILES_TOTAL 2048
#define NCTA 296

// ---------------- device scratch ----------------
__device__ float g_s[NB * CIN];
__device__ float g_demod[NB * COUT];
__device__ float g_wsq[COUT * CIN];
__device__ __align__(16) __half g_xm[XM_ELEMS];          // x*s fp16, [n][c16][p][16]
__device__ __align__(16) __half g_wB[32 * 4 * 9 * 128 * 16]; // [c16][cotile][tap][co128][16ci]
__device__ __align__(16) __half g_zero[1024];            // 2 KB zeros

// ---------------- PTX helpers ----------------
__device__ __forceinline__ uint32_t smem_u32(const void* p) {
    uint32_t a;
    asm("{ .reg .u64 t; cvta.to.shared.u64 t, %1; cvt.u32.u64 %0, t; }" : "=r"(a) : "l"(p));
    return a;
}
#define MBAR_INIT(mb, c) asm volatile("mbarrier.init.shared.b64 [%0], %1;" :: "r"((uint32_t)(mb)), "r"((uint32_t)(c)) : "memory")
#define MBAR_ARRIVE(mb)  asm volatile("mbarrier.arrive.shared.b64 _, [%0];" :: "r"((uint32_t)(mb)) : "memory")
#define MBAR_EXPECT(mb, n) asm volatile("mbarrier.arrive.expect_tx.shared.b64 _, [%0], %1;" :: "r"((uint32_t)(mb)), "r"((uint32_t)(n)) : "memory")
#define FENCE_ASYNC()    asm volatile("fence.proxy.async.shared::cta;" ::: "memory")

#define MBAR_WAIT(mb, ph) do {                                                   \
    uint32_t _mb = (uint32_t)(mb); uint32_t _ph = (uint32_t)(ph); uint32_t _dn;  \
    asm volatile("{ .reg .pred p; mbarrier.try_wait.parity.acquire.cta.shared::cta.b64 p, [%1], %2; selp.b32 %0, 1, 0, p; }" \
        : "=r"(_dn) : "r"(_mb), "r"(_ph) : "memory");                            \
    if (!_dn) {                                                                  \
        asm volatile("{ .reg .pred P1;\n"                                        \
            "WL_%=: mbarrier.try_wait.parity.acquire.cta.shared::cta.b64 P1, [%0], %1, 0x989680;\n" \
            "@P1 bra.uni WD_%=;\n bra.uni WL_%=;\n WD_%=: }"                     \
            :: "r"(_mb), "r"(_ph) : "memory");                                   \
    }                                                                            \
} while (0)

#define BULK(dst, src, sz, mb) \
    asm volatile("cp.async.bulk.shared::cta.global.mbarrier::complete_tx::bytes [%0], [%1], %2, [%3];" \
        :: "r"((uint32_t)(dst)), "l"(src), "r"((uint32_t)(sz)), "r"((uint32_t)(mb)) : "memory")

#define LDSM4(r, a) \
    asm volatile("ldmatrix.sync.aligned.m8n8.x4.shared.b16 {%0,%1,%2,%3}, [%4];" \
        : "=r"((r)[0]), "=r"((r)[1]), "=r"((r)[2]), "=r"((r)[3]) : "r"(a))

__device__ __forceinline__ void mma_f16(float* c, const uint32_t* a, const uint32_t* b) {
    asm volatile("mma.sync.aligned.m16n8k16.row.col.f32.f16.f16.f32 "
        "{%0,%1,%2,%3}, {%4,%5,%6,%7}, {%8,%9}, {%0,%1,%2,%3};"
        : "+f"(c[0]), "+f"(c[1]), "+f"(c[2]), "+f"(c[3])
        : "r"(a[0]), "r"(a[1]), "r"(a[2]), "r"(a[3]), "r"(b[0]), "r"(b[1]));
}

// ---------------- prep kernels ----------------
__global__ void k_style(const float* __restrict__ style,
                        const float* __restrict__ style_w,
                        const float* __restrict__ style_b) {
    int n = blockIdx.x, ci = threadIdx.x;
    const float* srow = style + n * STY;
    const float* wrow = style_w + ci * STY;
    float acc = 0.f;
    #pragma unroll 8
    for (int j = 0; j < STY; j++) acc += srow[j] * wrow[j];
    g_s[n * CIN + ci] = acc + style_b[ci];
}

__global__ void k_wprep(const float* __restrict__ weight) {
    int id = blockIdx.x * 256 + threadIdx.x;
    int ci = id & 511, co = id >> 9;
    const float* wp = weight + (size_t)(co * CIN + ci) * 9;
    int c16 = ci >> 4, cil = ci & 15;
    int cotile = co >> 7, col = co & 127;
    float s = 0.f;
    #pragma unroll
    for (int tap = 0; tap < 9; tap++) {
        float v = wp[tap];
        s += v * v;
        g_wB[(((size_t)(c16 * 4 + cotile) * 9 + tap) * 128 + col) * 16 + cil] =
            __float2half_rn(v);
    }
    g_wsq[co * CIN + ci] = s;
}

__global__ void k_demod() {
    int co = blockIdx.x, n = blockIdx.y;
    __shared__ float red[128];
    float acc = 0.f;
    for (int ci = threadIdx.x; ci < CIN; ci += 128) {
        float s = g_s[n * CIN + ci];
        acc += g_wsq[co * CIN + ci] * s * s;
    }
    red[threadIdx.x] = acc;
    __syncthreads();
    for (int st = 64; st > 0; st >>= 1) {
        if (threadIdx.x < st) red[threadIdx.x] += red[threadIdx.x + st];
        __syncthreads();
    }
    if (threadIdx.x == 0) g_demod[n * COUT + co] = rsqrtf(red[0] + EPSV);
}

__global__ void k_xmod(const float* __restrict__ x) {
    int b   = blockIdx.x;
    int n   = b >> 9;
    int c16 = (b >> 4) & 31;
    int pb  = b & 15;
    int p   = pb * 256 + threadIdx.x;
    const float* sp = g_s + n * CIN + c16 * 16;
    const float* xp = x + (size_t)(n * CIN + c16 * 16) * HW + p;
    uint32_t hi[8];
    #pragma unroll
    for (int j = 0; j < 8; j++) {
        float v0 = xp[(size_t)(2 * j) * HW]     * sp[2 * j];
        float v1 = xp[(size_t)(2 * j + 1) * HW] * sp[2 * j + 1];
        __half2 hp = __halves2half2(__float2half_rn(v0), __float2half_rn(v1));
        hi[j] = *reinterpret_cast<uint32_t*>(&hp);
    }
    size_t ob = ((size_t)(n * 32 + c16) * HW + p) * 16;
    uint4* oh = reinterpret_cast<uint4*>(g_xm + ob);
    oh[0] = make_uint4(hi[0], hi[1], hi[2], hi[3]);
    oh[1] = make_uint4(hi[4], hi[5], hi[6], hi[7]);
}

// ------- main HMMA kernel: persistent, 128 thr, 2 CTA/SM, 2-stage ring -------
// Tile: 128 px (2 image rows) x 128 cout. 4 warps (2 px-rows x 2 co-halves).
// A halo per stage: [4 rows][66][16] halfs = 8448 B. B: [9][128][16] = 36864 B.
#define A_BYTES   8448
#define B_BYTES   36864
#define SSTRIDE   (A_BYTES + B_BYTES)            // 45312
#define SM_DATA   1024
#define SM_EPI    (SM_DATA + 2 * SSTRIDE)        // 91648
#define SMEM_TOTAL (SM_EPI + 4 * 2048)           // 99840
#define EXPECT_B  (4 * 2048 + B_BYTES)           // 45056

// tile decode: n = tile>>7; rem = tile&127; ptile = rem>>2 (2 rows); cotile = rem&3
__device__ __forceinline__ void issue_stage(uint32_t sb, int ls, int bx) {
    int tord = ls >> 5, c16 = ls & 31;
    int tile = bx + NCTA * tord;
    int n = tile >> 7, rem = tile & 127;
    int h0 = (rem >> 2) * 2;
    int cotile = rem & 3;
    int slot = ls & 1;
    uint32_t sa = sb + SM_DATA + slot * SSTRIDE;
    uint32_t mb = sb + slot * 8;
    MBAR_EXPECT(mb, EXPECT_B);
    const __half* xbase = g_xm + ((size_t)(n * 32 + c16) * HW) * 16;
    #pragma unroll
    for (int r = 0; r < 4; r++) {
        int hh = h0 - 1 + r;
        const __half* src = ((unsigned)hh < 64u) ? (xbase + (size_t)hh * 64 * 16)
                                                 : g_zero;
        BULK(sa + (r * 66 + 1) * 32, src, 2048, mb);
    }
    BULK(sa + A_BYTES, g_wB + (size_t)(c16 * 4 + cotile) * 18432, B_BYTES, mb);
}

#define LOADB(BH, addr)                                           \
    do {                                                          \
        uint32_t _bb = (addr);                                    \
        uint32_t _bq[4];                                          \
        LDSM4(_bq, _bb);          (BH)[0][0]=_bq[0]; (BH)[0][1]=_bq[1]; (BH)[1][0]=_bq[2]; (BH)[1][1]=_bq[3]; \
        LDSM4(_bq, _bb + 512);    (BH)[2][0]=_bq[0]; (BH)[2][1]=_bq[1]; (BH)[3][0]=_bq[2]; (BH)[3][1]=_bq[3]; \
        LDSM4(_bq, _bb + 1024);   (BH)[4][0]=_bq[0]; (BH)[4][1]=_bq[1]; (BH)[5][0]=_bq[2]; (BH)[5][1]=_bq[3]; \
        LDSM4(_bq, _bb + 1536);   (BH)[6][0]=_bq[0]; (BH)[6][1]=_bq[1]; (BH)[7][0]=_bq[2]; (BH)[7][1]=_bq[3]; \
    } while (0)

// One tap. slotv compile-time (stage parity). A offsets same constants as the
// 6-row halo since row stride (66*32) is unchanged.
#define TAPB(lsv, slotv, tapv, TOFF, CUR, NXT, ISLAST)                           \
    do {                                                                         \
        uint32_t _saA = sb + SM_DATA + (slotv) * SSTRIDE;                        \
        uint32_t _aa = _saA + aoff0 + (TOFF);                                    \
        uint32_t ah0[4], ah1[4], ah2[4], ah3[4];                                 \
        LDSM4(ah0, _aa);                                                         \
        LDSM4(ah1, _aa + 512);                                                   \
        LDSM4(ah2, _aa + 1024);                                                  \
        LDSM4(ah3, _aa + 1536);                                                  \
        if (ISLAST) { if (lane == 0) MBAR_ARRIVE(sb + 64 + (slotv) * 8); }       \
        _Pragma("unroll")                                                        \
        for (int bn = 0; bn < 8; bn++) mma_f16(acc[0][bn], ah0, CUR[bn]);        \
        _Pragma("unroll")                                                        \
        for (int bn = 0; bn < 8; bn++) mma_f16(acc[1][bn], ah1, CUR[bn]);        \
        if (!(ISLAST)) {                                                         \
            LOADB(NXT, _saA + A_BYTES + ((tapv) + 1) * 4096 + boff);             \
        } else if ((lsv) + 1 < nls) {                                            \
            MBAR_WAIT(sb + (1 - (slotv)) * 8, (((lsv) + 1) >> 1) & 1);           \
            LOADB(NXT, sb + SM_DATA + (1 - (slotv)) * SSTRIDE + A_BYTES + boff); \
        }                                                                        \
        _Pragma("unroll")                                                        \
        for (int bn = 0; bn < 8; bn++) mma_f16(acc[2][bn], ah2, CUR[bn]);        \
        _Pragma("unroll")                                                        \
        for (int bn = 0; bn < 8; bn++) mma_f16(acc[3][bn], ah3, CUR[bn]);        \
        if ((ISLAST) && (lsv) + 2 < nls) {                                       \
            if (wid == ((lsv) & 3) && lane == 0) {                               \
                MBAR_WAIT(sb + 64 + (slotv) * 8, ((lsv) >> 1) & 1);              \
                issue_stage(sb, (lsv) + 2, bx);                                  \
            }                                                                    \
        }                                                                        \
    } while (0)

// A-row stride is 66*32 = 2112 B; tap offsets (dh*66+dw)*32
#define STAGE(lsv, slotv, B0, B1)                          \
    do {                                                   \
        TAPB(lsv, slotv, 0, -2144, B0, B1, 0);             \
        TAPB(lsv, slotv, 1, -2112, B1, B0, 0);             \
        TAPB(lsv, slotv, 2, -2080, B0, B1, 0);             \
        TAPB(lsv, slotv, 3,   -32, B1, B0, 0);             \
        TAPB(lsv, slotv, 4,     0, B0, B1, 0);             \
        TAPB(lsv, slotv, 5,    32, B1, B0, 0);             \
        TAPB(lsv, slotv, 6,  2080, B0, B1, 0);             \
        TAPB(lsv, slotv, 7,  2112, B1, B0, 0);             \
        TAPB(lsv, slotv, 8,  2144, B0, B1, 1);             \
    } while (0)

__global__ void __launch_bounds__(128, 2)
k_main(const float* __restrict__ noise,
       const float* __restrict__ nw_p,
       float* __restrict__ out) {
    extern __shared__ __align__(1024) char smem[];
    uint32_t sb = smem_u32(smem);
    int t = threadIdx.x, wid = t >> 5, lane = t & 31;
    int wm = wid & 1, wn = wid >> 1;
    int bx = blockIdx.x;

    int ntiles = (NTILES_TOTAL - bx + NCTA - 1) / NCTA;
    int nls = ntiles * 32;

    if (t == 0) {
        #pragma unroll
        for (int s = 0; s < 2; s++) {
            MBAR_INIT(sb + s * 8, 1);        // full
            MBAR_INIT(sb + 64 + s * 8, 4);   // empty: 4 warps
        }
    }
    // zero both A regions (halo columns stay zero; rows always bulk-filled)
    {
        uint32_t zb = sb + SM_DATA;
        for (int i = t * 16; i < A_BYTES; i += 2048) {
            asm volatile(
                "st.shared.v4.b32 [%0], {%2,%2,%2,%2};\n\t"
                "st.shared.v4.b32 [%1], {%2,%2,%2,%2};"
                :: "r"(zb + i), "r"(zb + SSTRIDE + i), "r"(0u) : "memory");
        }
    }
    __syncthreads();
    if (lane == 0 && wid < 2) {
        FENCE_ASYNC();
        issue_stage(sb, wid, bx);
    }

    float acc[4][8][4];
    #pragma unroll
    for (int a = 0; a < 4; a++)
        #pragma unroll
        for (int b = 0; b < 8; b++)
            #pragma unroll
            for (int c = 0; c < 4; c++) acc[a][b][c] = 0.f;

    int bg = lane >> 3, br = lane & 7;
    uint32_t boff = (uint32_t)(wn * 64 + (bg >> 1) * 8 + br) * 32
                  + (uint32_t)(bg & 1) * 16;
    uint32_t aoff0 = (uint32_t)((wm + 1) * 66 + (lane & 15) + 1) * 32
                   + (uint32_t)(lane >> 4) * 16;

    uint32_t bhA[8][2], bhB[8][2];
    float nw = nw_p[0];

    // prologue
    MBAR_WAIT(sb + 0, 0);
    LOADB(bhA, sb + SM_DATA + A_BYTES + boff);

    int tile = bx;
    for (int tord = 0; tord < ntiles; tord++, tile += NCTA) {
        int lsbase = tord * 32;
        for (int cc = 0; cc < 32; cc += 2) {
            STAGE(lsbase + cc,     0, bhA, bhB);
            STAGE(lsbase + cc + 1, 1, bhB, bhA);
        }

        // ---- warp-local epilogue (overlaps next tile's bulk loads) ----
        {
            int n   = tile >> 7;
            int rem = tile & 127;
            int p0  = (rem >> 2) * 128;
            int co0 = (rem & 3) * 128;

            int q = lane & 3, rr = lane >> 2;
            int pxbase = p0 + wm * 64 + q * 16;
            float nzs[16];
            #pragma unroll
            for (int j = 0; j < 16; j++) nzs[j] = nw * noise[n * HW + pxbase + j];

            float* wsm = reinterpret_cast<float*>(smem + SM_EPI + wid * 2048);
            const float* dmrow = g_demod + n * COUT;

            #pragma unroll
            for (int g = 0; g < 8; g++) {
                #pragma unroll
                for (int am = 0; am < 4; am++) {
                    int px = am * 16 + (lane >> 2);
                    int col = (lane & 3) * 2;
                    wsm[col * 64 + px]           = acc[am][g][0];
                    wsm[(col + 1) * 64 + px]     = acc[am][g][1];
                    wsm[col * 64 + px + 8]       = acc[am][g][2];
                    wsm[(col + 1) * 64 + px + 8] = acc[am][g][3];
                }
                __syncwarp();
                int co = co0 + wn * 64 + g * 8 + rr;
                float d = dmrow[co];
                float* op = out + ((size_t)(n * COUT + co)) * HW + pxbase;
                const float* srp = wsm + rr * 64 + q * 16;
                #pragma unroll
                for (int j4 = 0; j4 < 4; j4++) {
                    float4 v = *reinterpret_cast<const float4*>(srp + j4 * 4);
                    float r0 = v.x * d + nzs[j4 * 4 + 0];
                    float r1 = v.y * d + nzs[j4 * 4 + 1];
                    float r2 = v.z * d + nzs[j4 * 4 + 2];
                    float r3 = v.w * d + nzs[j4 * 4 + 3];
                    r0 = (r0 >= 0.f) ? r0 : 0.2f * r0;
                    r1 = (r1 >= 0.f) ? r1 : 0.2f * r1;
                    r2 = (r2 >= 0.f) ? r2 : 0.2f * r2;
                    r3 = (r3 >= 0.f) ? r3 : 0.2f * r3;
                    *reinterpret_cast<float4*>(op + j4 * 4) = make_float4(r0, r1, r2, r3);
                }
                __syncwarp();
            }
        }

        #pragma unroll
        for (int a = 0; a < 4; a++)
            #pragma unroll
            for (int b = 0; b < 8; b++)
                #pragma unroll
                for (int c = 0; c < 4; c++) acc[a][b][c] = 0.f;
    }
}

// ---------------------------------------------------------------------------
extern "C" void kernel_launch(void* const* d_in, const int* in_sizes, int n_in,
                              void* d_out, int out_size) {
    const float* x            = (const float*)d_in[0];
    const float* style        = (const float*)d_in[1];
    const float* noise        = (const float*)d_in[2];
    const float* weight       = (const float*)d_in[3];
    const float* style_w      = (const float*)d_in[4];
    const float* style_b      = (const float*)d_in[5];
    const float* noise_weight = (const float*)d_in[6];
    float* out = (float*)d_out;

    cudaFuncSetAttribute(k_main, cudaFuncAttributeMaxDynamicSharedMemorySize, SMEM_TOTAL);

    k_style<<<NB, CIN>>>(style, style_w, style_b);
    k_wprep<<<1024, 256>>>(weight);
    {
        dim3 g(COUT, NB);
        k_demod<<<g, 128>>>();
    }
    k_xmod<<<8192, 256>>>(x);
    k_main<<<NCTA, 128, SMEM_TOTAL>>>(noise, noise_weight, out);
}

// round 13
// speedup vs baseline: 1.0528x; 1.0480x over previous
#include <cuda_runtime.h>
#include <cuda_fp16.h>
#include <cstdint>

#define NB    16
#define CIN   512
#define COUT  512
#define STY   512
#define HW    4096
#define EPSV  1e-8f

#define XM_ELEMS (NB * 32 * HW * 16)
#define NTILES_TOTAL 1024
#define NCTA 148

// ---------------- device scratch ----------------
__device__ float g_s[NB * CIN];
__device__ float g_demod[NB * COUT];
__device__ float g_wsq[COUT * CIN];
__device__ __align__(16) __half g_xm[XM_ELEMS];          // x*s fp16, swizzled halves
__device__ __align__(16) __half g_wB[32 * 4 * 9 * 128 * 16]; // swizzled halves
__device__ __align__(16) __half g_zero[1024];            // 2 KB zeros

// ---------------- PTX helpers ----------------
__device__ __forceinline__ uint32_t smem_u32(const void* p) {
    uint32_t a;
    asm("{ .reg .u64 t; cvta.to.shared.u64 t, %1; cvt.u32.u64 %0, t; }" : "=r"(a) : "l"(p));
    return a;
}
#define MBAR_INIT(mb, c) asm volatile("mbarrier.init.shared.b64 [%0], %1;" :: "r"((uint32_t)(mb)), "r"((uint32_t)(c)) : "memory")
#define MBAR_ARRIVE(mb)  asm volatile("mbarrier.arrive.shared.b64 _, [%0];" :: "r"((uint32_t)(mb)) : "memory")
#define MBAR_EXPECT(mb, n) asm volatile("mbarrier.arrive.expect_tx.shared.b64 _, [%0], %1;" :: "r"((uint32_t)(mb)), "r"((uint32_t)(n)) : "memory")
#define FENCE_ASYNC()    asm volatile("fence.proxy.async.shared::cta;" ::: "memory")

#define MBAR_WAIT(mb, ph) do {                                                   \
    uint32_t _mb = (uint32_t)(mb); uint32_t _ph = (uint32_t)(ph); uint32_t _dn;  \
    asm volatile("{ .reg .pred p; mbarrier.try_wait.parity.acquire.cta.shared::cta.b64 p, [%1], %2; selp.b32 %0, 1, 0, p; }" \
        : "=r"(_dn) : "r"(_mb), "r"(_ph) : "memory");                            \
    if (!_dn) {                                                                  \
        asm volatile("{ .reg .pred P1;\n"                                        \
            "WL_%=: mbarrier.try_wait.parity.acquire.cta.shared::cta.b64 P1, [%0], %1, 0x989680;\n" \
            "@P1 bra.uni WD_%=;\n bra.uni WL_%=;\n WD_%=: }"                     \
            :: "r"(_mb), "r"(_ph) : "memory");                                   \
    }                                                                            \
} while (0)

#define BULK(dst, src, sz, mb) \
    asm volatile("cp.async.bulk.shared::cta.global.mbarrier::complete_tx::bytes [%0], [%1], %2, [%3];" \
        :: "r"((uint32_t)(dst)), "l"(src), "r"((uint32_t)(sz)), "r"((uint32_t)(mb)) : "memory")

#define LDSM4(r, a) \
    asm volatile("ldmatrix.sync.aligned.m8n8.x4.shared.b16 {%0,%1,%2,%3}, [%4];" \
        : "=r"((r)[0]), "=r"((r)[1]), "=r"((r)[2]), "=r"((r)[3]) : "r"(a))

__device__ __forceinline__ void mma_f16(float* c, const uint32_t* a, const uint32_t* b) {
    asm volatile("mma.sync.aligned.m16n8k16.row.col.f32.f16.f16.f32 "
        "{%0,%1,%2,%3}, {%4,%5,%6,%7}, {%8,%9}, {%0,%1,%2,%3};"
        : "+f"(c[0]), "+f"(c[1]), "+f"(c[2]), "+f"(c[3])
        : "r"(a[0]), "r"(a[1]), "r"(a[2]), "r"(a[3]), "r"(b[0]), "r"(b[1]));
}

// ---------------- prep kernels ----------------
__global__ void k_style(const float* __restrict__ style,
                        const float* __restrict__ style_w,
                        const float* __restrict__ style_b) {
    int n = blockIdx.x, ci = threadIdx.x;
    const float* srow = style + n * STY;
    const float* wrow = style_w + ci * STY;
    float acc = 0.f;
    #pragma unroll 8
    for (int j = 0; j < STY; j++) acc += srow[j] * wrow[j];
    g_s[n * CIN + ci] = acc + style_b[ci];
}

// weights -> fp16 [c16][cotile][tap][co128][16ci], halves swapped when co&4
__global__ void k_wprep(const float* __restrict__ weight) {
    int id = blockIdx.x * 256 + threadIdx.x;
    int ci = id & 511, co = id >> 9;
    const float* wp = weight + (size_t)(co * CIN + ci) * 9;
    int c16 = ci >> 4, cil = ci & 15;
    int cotile = co >> 7, col = co & 127;
    int cil_sw = (col & 4) ? (cil ^ 8) : cil;    // bank-conflict swizzle
    float s = 0.f;
    #pragma unroll
    for (int tap = 0; tap < 9; tap++) {
        float v = wp[tap];
        s += v * v;
        g_wB[(((size_t)(c16 * 4 + cotile) * 9 + tap) * 128 + col) * 16 + cil_sw] =
            __float2half_rn(v);
    }
    g_wsq[co * CIN + ci] = s;
}

__global__ void k_demod() {
    int co = blockIdx.x, n = blockIdx.y;
    __shared__ float red[128];
    float acc = 0.f;
    for (int ci = threadIdx.x; ci < CIN; ci += 128) {
        float s = g_s[n * CIN + ci];
        acc += g_wsq[co * CIN + ci] * s * s;
    }
    red[threadIdx.x] = acc;
    __syncthreads();
    for (int st = 64; st > 0; st >>= 1) {
        if (threadIdx.x < st) red[threadIdx.x] += red[threadIdx.x + st];
        __syncthreads();
    }
    if (threadIdx.x == 0) g_demod[n * COUT + co] = rsqrtf(red[0] + EPSV);
}

// x*s -> fp16 [n][c16][p][16], halves swapped when halo-col (w+1)&4
__global__ void k_xmod(const float* __restrict__ x) {
    int b   = blockIdx.x;
    int n   = b >> 9;
    int c16 = (b >> 4) & 31;
    int pb  = b & 15;
    int p   = pb * 256 + threadIdx.x;
    const float* sp = g_s + n * CIN + c16 * 16;
    const float* xp = x + (size_t)(n * CIN + c16 * 16) * HW + p;
    uint32_t hi[8];
    #pragma unroll
    for (int j = 0; j < 8; j++) {
        float v0 = xp[(size_t)(2 * j) * HW]     * sp[2 * j];
        float v1 = xp[(size_t)(2 * j + 1) * HW] * sp[2 * j + 1];
        __half2 hp = __halves2half2(__float2half_rn(v0), __float2half_rn(v1));
        hi[j] = *reinterpret_cast<uint32_t*>(&hp);
    }
    size_t ob = ((size_t)(n * 32 + c16) * HW + p) * 16;
    uint4* oh = reinterpret_cast<uint4*>(g_xm + ob);
    uint4 lo4 = make_uint4(hi[0], hi[1], hi[2], hi[3]);
    uint4 hi4 = make_uint4(hi[4], hi[5], hi[6], hi[7]);
    if (((p & 63) + 1) & 4) {     // halo col c = w+1; swap halves when c&4
        oh[0] = hi4; oh[1] = lo4;
    } else {
        oh[0] = lo4; oh[1] = hi4;
    }
}

// ---------------- main HMMA kernel (persistent, 2-stage, swizzled) -----------
#define A_BYTES   12672      // [6][66][16] halfs
#define B_BYTES   36864      // [9][128][16] halfs
#define SSTRIDE   (A_BYTES + B_BYTES)            // 49536
#define SM_DATA   1024
#define SM_EPI    (SM_DATA + 2 * SSTRIDE)        // 100096
#define SMEM_TOTAL (SM_EPI + 8 * 2048)           // 116480
#define EXPECT_B  (6 * 2048 + B_BYTES)           // 49152

__device__ __forceinline__ void issue_stage(uint32_t sb, int ls, int bx) {
    int tord = ls >> 5, c16 = ls & 31;
    int tile = bx + NCTA * tord;
    int n = tile >> 6, rem = tile & 63;
    int h0 = (rem >> 2) * 4;
    int cotile = rem & 3;
    int slot = ls & 1;
    uint32_t sa = sb + SM_DATA + slot * SSTRIDE;
    uint32_t mb = sb + slot * 8;
    MBAR_EXPECT(mb, EXPECT_B);
    const __half* xbase = g_xm + ((size_t)(n * 32 + c16) * HW) * 16;
    #pragma unroll
    for (int r = 0; r < 6; r++) {
        int hh = h0 - 1 + r;
        const __half* src = ((unsigned)hh < 64u) ? (xbase + (size_t)hh * 64 * 16)
                                                 : g_zero;
        BULK(sa + (r * 66 + 1) * 32, src, 2048, mb);
    }
    BULK(sa + A_BYTES, g_wB + (size_t)(c16 * 4 + cotile) * 18432, B_BYTES, mb);
}

#define LOADB(BH, addr)                                           \
    do {                                                          \
        uint32_t _bb = (addr);                                    \
        uint32_t _bq[4];                                          \
        LDSM4(_bq, _bb);          (BH)[0][0]=_bq[0]; (BH)[0][1]=_bq[1]; (BH)[1][0]=_bq[2]; (BH)[1][1]=_bq[3]; \
        LDSM4(_bq, _bb + 512);    (BH)[2][0]=_bq[0]; (BH)[2][1]=_bq[1]; (BH)[3][0]=_bq[2]; (BH)[3][1]=_bq[3]; \
        LDSM4(_bq, _bb + 1024);   (BH)[4][0]=_bq[0]; (BH)[4][1]=_bq[1]; (BH)[5][0]=_bq[2]; (BH)[5][1]=_bq[3]; \
        LDSM4(_bq, _bb + 1536);   (BH)[6][0]=_bq[0]; (BH)[6][1]=_bq[1]; (BH)[7][0]=_bq[2]; (BH)[7][1]=_bq[3]; \
    } while (0)

// One tap. ROFF = dh*2112 (compile-time); AIDX selects the per-dw lane offset.
#define TAPB(lsv, slotv, tapv, ROFF, AIDX, CUR, NXT, ISLAST)                     \
    do {                                                                         \
        uint32_t _saA = sb + SM_DATA + (slotv) * SSTRIDE;                        \
        uint32_t _aa = _saA + aof[AIDX] + (ROFF);                                \
        uint32_t ah0[4], ah1[4], ah2[4], ah3[4];                                 \
        LDSM4(ah0, _aa);                                                         \
        LDSM4(ah1, _aa + 512);                                                   \
        LDSM4(ah2, _aa + 1024);                                                  \
        LDSM4(ah3, _aa + 1536);                                                  \
        if (ISLAST) { if (lane == 0) MBAR_ARRIVE(sb + 64 + (slotv) * 8); }       \
        _Pragma("unroll")                                                        \
        for (int bn = 0; bn < 8; bn++) mma_f16(acc[0][bn], ah0, CUR[bn]);        \
        _Pragma("unroll")                                                        \
        for (int bn = 0; bn < 8; bn++) mma_f16(acc[1][bn], ah1, CUR[bn]);        \
        if (!(ISLAST)) {                                                         \
            LOADB(NXT, _saA + A_BYTES + ((tapv) + 1) * 4096 + boff);             \
        } else if ((lsv) + 1 < nls) {                                            \
            MBAR_WAIT(sb + (1 - (slotv)) * 8, (((lsv) + 1) >> 1) & 1);           \
            LOADB(NXT, sb + SM_DATA + (1 - (slotv)) * SSTRIDE + A_BYTES + boff); \
        }                                                                        \
        _Pragma("unroll")                                                        \
        for (int bn = 0; bn < 8; bn++) mma_f16(acc[2][bn], ah2, CUR[bn]);        \
        _Pragma("unroll")                                                        \
        for (int bn = 0; bn < 8; bn++) mma_f16(acc[3][bn], ah3, CUR[bn]);        \
        if ((ISLAST) && (lsv) + 2 < nls) {                                       \
            if (wid == ((lsv) & 7) && lane == 0) {                               \
                MBAR_WAIT(sb + 64 + (slotv) * 8, ((lsv) >> 1) & 1);              \
                issue_stage(sb, (lsv) + 2, bx);                                  \
            }                                                                    \
        }                                                                        \
    } while (0)

// taps: (dh,dw) row-offset dh*2112, AIDX = dw+1
#define STAGE(lsv, slotv, B0, B1)                          \
    do {                                                   \
        TAPB(lsv, slotv, 0, -2112, 0, B0, B1, 0);          \
        TAPB(lsv, slotv, 1, -2112, 1, B1, B0, 0);          \
        TAPB(lsv, slotv, 2, -2112, 2, B0, B1, 0);          \
        TAPB(lsv, slotv, 3,     0, 0, B1, B0, 0);          \
        TAPB(lsv, slotv, 4,     0, 1, B0, B1, 0);          \
        TAPB(lsv, slotv, 5,     0, 2, B1, B0, 0);          \
        TAPB(lsv, slotv, 6,  2112, 0, B0, B1, 0);          \
        TAPB(lsv, slotv, 7,  2112, 1, B1, B0, 0);          \
        TAPB(lsv, slotv, 8,  2112, 2, B0, B1, 1);          \
    } while (0)

__global__ void __launch_bounds__(256, 1)
k_main(const float* __restrict__ noise,
       const float* __restrict__ nw_p,
       float* __restrict__ out) {
    extern __shared__ __align__(1024) char smem[];
    uint32_t sb = smem_u32(smem);
    int t = threadIdx.x, wid = t >> 5, lane = t & 31;
    int wm = wid & 3, wn = wid >> 2;
    int bx = blockIdx.x;

    int ntiles = (NTILES_TOTAL - bx + NCTA - 1) / NCTA;
    int nls = ntiles * 32;

    if (t == 0) {
        #pragma unroll
        for (int s = 0; s < 2; s++) {
            MBAR_INIT(sb + s * 8, 1);
            MBAR_INIT(sb + 64 + s * 8, 8);
        }
    }
    {
        uint32_t zb = sb + SM_DATA;
        for (int i = t * 16; i < A_BYTES; i += 4096) {
            asm volatile(
                "st.shared.v4.b32 [%0], {%2,%2,%2,%2};\n\t"
                "st.shared.v4.b32 [%1], {%2,%2,%2,%2};"
                :: "r"(zb + i), "r"(zb + SSTRIDE + i), "r"(0u) : "memory");
        }
    }
    __syncthreads();
    if (lane == 0 && wid < 2) {
        FENCE_ASYNC();
        issue_stage(sb, wid, bx);
    }

    float acc[4][8][4];
    #pragma unroll
    for (int a = 0; a < 4; a++)
        #pragma unroll
        for (int b = 0; b < 8; b++)
            #pragma unroll
            for (int c = 0; c < 4; c++) acc[a][b][c] = 0.f;

    // swizzled lane offsets
    int bg = lane >> 3, br = lane & 7;
    uint32_t boff = (uint32_t)((wn * 64 + (bg >> 1) * 8 + br) * 32)
                  + (uint32_t)((((bg & 1) ^ ((br >> 2) & 1)) ) * 16);
    int pxl = lane & 15, hh = lane >> 4;
    uint32_t aof[3];
    #pragma unroll
    for (int d = 0; d < 3; d++) {
        int c = pxl + d;              // halo col for dw = d-1
        aof[d] = (uint32_t)(((wm + 1) * 66 + c) * 32)
               + (uint32_t)((hh ^ ((c >> 2) & 1)) * 16);
    }

    uint32_t bhA[8][2], bhB[8][2];
    float nw = nw_p[0];

    // prologue
    MBAR_WAIT(sb + 0, 0);
    LOADB(bhA, sb + SM_DATA + A_BYTES + boff);

    int tile = bx;
    for (int tord = 0; tord < ntiles; tord++, tile += NCTA) {
        int lsbase = tord * 32;
        for (int cc = 0; cc < 32; cc += 2) {
            STAGE(lsbase + cc,     0, bhA, bhB);
            STAGE(lsbase + cc + 1, 1, bhB, bhA);
        }

        // ---- warp-local epilogue ----
        {
            int n   = tile >> 6;
            int rem = tile & 63;
            int p0  = (rem >> 2) * 256;
            int co0 = (rem & 3) * 128;

            int q = lane & 3, rr = lane >> 2;
            int pxbase = p0 + wm * 64 + q * 16;
            float nzs[16];
            #pragma unroll
            for (int j = 0; j < 16; j++) nzs[j] = nw * noise[n * HW + pxbase + j];

            float* wsm = reinterpret_cast<float*>(smem + SM_EPI + wid * 2048);
            const float* dmrow = g_demod + n * COUT;

            #pragma unroll
            for (int g = 0; g < 8; g++) {
                #pragma unroll
                for (int am = 0; am < 4; am++) {
                    int px = am * 16 + (lane >> 2);
                    int col = (lane & 3) * 2;
                    wsm[col * 64 + px]           = acc[am][g][0];
                    wsm[(col + 1) * 64 + px]     = acc[am][g][1];
                    wsm[col * 64 + px + 8]       = acc[am][g][2];
                    wsm[(col + 1) * 64 + px + 8] = acc[am][g][3];
                }
                __syncwarp();
                int co = co0 + wn * 64 + g * 8 + rr;
                float d = dmrow[co];
                float* op = out + ((size_t)(n * COUT + co)) * HW + pxbase;
                const float* srp = wsm + rr * 64 + q * 16;
                #pragma unroll
                for (int j4 = 0; j4 < 4; j4++) {
                    float4 v = *reinterpret_cast<const float4*>(srp + j4 * 4);
                    float r0 = v.x * d + nzs[j4 * 4 + 0];
                    float r1 = v.y * d + nzs[j4 * 4 + 1];
                    float r2 = v.z * d + nzs[j4 * 4 + 2];
                    float r3 = v.w * d + nzs[j4 * 4 + 3];
                    r0 = (r0 >= 0.f) ? r0 : 0.2f * r0;
                    r1 = (r1 >= 0.f) ? r1 : 0.2f * r1;
                    r2 = (r2 >= 0.f) ? r2 : 0.2f * r2;
                    r3 = (r3 >= 0.f) ? r3 : 0.2f * r3;
                    *reinterpret_cast<float4*>(op + j4 * 4) = make_float4(r0, r1, r2, r3);
                }
                __syncwarp();
            }
        }

        #pragma unroll
        for (int a = 0; a < 4; a++)
            #pragma unroll
            for (int b = 0; b < 8; b++)
                #pragma unroll
                for (int c = 0; c < 4; c++) acc[a][b][c] = 0.f;
    }
}

// ---------------------------------------------------------------------------
extern "C" void kernel_launch(void* const* d_in, const int* in_sizes, int n_in,
                              void* d_out, int out_size) {
    const float* x            = (const float*)d_in[0];
    const float* style        = (const float*)d_in[1];
    const float* noise        = (const float*)d_in[2];
    const float* weight       = (const float*)d_in[3];
    const float* style_w      = (const float*)d_in[4];
    const float* style_b      = (const float*)d_in[5];
    const float* noise_weight = (const float*)d_in[6];
    float* out = (float*)d_out;

    cudaFuncSetAttribute(k_main, cudaFuncAttributeMaxDynamicSharedMemorySize, SMEM_TOTAL);

    k_style<<<NB, CIN>>>(style, style_w, style_b);
    k_wprep<<<1024, 256>>>(weight);
    {
        dim3 g(COUT, NB);
        k_demod<<<g, 128>>>();
    }
    k_xmod<<<8192, 256>>>(x);
    k_main<<<NCTA, 256, SMEM_TOTAL>>>(noise, noise_weight, out);
}

// round 14
// speedup vs baseline: 1.0675x; 1.0139x over previous
#include <cuda_runtime.h>
#include <cuda_fp16.h>
#include <cstdint>

#define NB    16
#define CIN   512
#define COUT  512
#define STY   512
#define HW    4096
#define EPSV  1e-8f

#define XM_ELEMS (NB * 32 * HW * 16)
#define NTILES_TOTAL 1024
#define NCTA 148

// ---------------- device scratch ----------------
__device__ float g_s[NB * CIN];
__device__ float g_demod[NB * COUT];
__device__ float g_wsq[COUT * CIN];
__device__ __align__(16) __half g_xm[XM_ELEMS];          // x*s fp16, swizzled halves
__device__ __align__(16) __half g_wB[32 * 4 * 9 * 128 * 16]; // swizzled halves
__device__ __align__(16) __half g_zero[1024];            // 2 KB zeros

// ---------------- PTX helpers ----------------
__device__ __forceinline__ uint32_t smem_u32(const void* p) {
    uint32_t a;
    asm("{ .reg .u64 t; cvta.to.shared.u64 t, %1; cvt.u32.u64 %0, t; }" : "=r"(a) : "l"(p));
    return a;
}
#define MBAR_INIT(mb, c) asm volatile("mbarrier.init.shared.b64 [%0], %1;" :: "r"((uint32_t)(mb)), "r"((uint32_t)(c)) : "memory")
#define MBAR_ARRIVE(mb)  asm volatile("mbarrier.arrive.shared.b64 _, [%0];" :: "r"((uint32_t)(mb)) : "memory")
#define MBAR_EXPECT(mb, n) asm volatile("mbarrier.arrive.expect_tx.shared.b64 _, [%0], %1;" :: "r"((uint32_t)(mb)), "r"((uint32_t)(n)) : "memory")
#define FENCE_ASYNC()    asm volatile("fence.proxy.async.shared::cta;" ::: "memory")

#define MBAR_WAIT(mb, ph) do {                                                   \
    uint32_t _mb = (uint32_t)(mb); uint32_t _ph = (uint32_t)(ph); uint32_t _dn;  \
    asm volatile("{ .reg .pred p; mbarrier.try_wait.parity.acquire.cta.shared::cta.b64 p, [%1], %2; selp.b32 %0, 1, 0, p; }" \
        : "=r"(_dn) : "r"(_mb), "r"(_ph) : "memory");                            \
    if (!_dn) {                                                                  \
        asm volatile("{ .reg .pred P1;\n"                                        \
            "WL_%=: mbarrier.try_wait.parity.acquire.cta.shared::cta.b64 P1, [%0], %1, 0x989680;\n" \
            "@P1 bra.uni WD_%=;\n bra.uni WL_%=;\n WD_%=: }"                     \
            :: "r"(_mb), "r"(_ph) : "memory");                                   \
    }                                                                            \
} while (0)

#define BULK(dst, src, sz, mb) \
    asm volatile("cp.async.bulk.shared::cta.global.mbarrier::complete_tx::bytes [%0], [%1], %2, [%3];" \
        :: "r"((uint32_t)(dst)), "l"(src), "r"((uint32_t)(sz)), "r"((uint32_t)(mb)) : "memory")

#define LDSM4(r, a) \
    asm volatile("ldmatrix.sync.aligned.m8n8.x4.shared.b16 {%0,%1,%2,%3}, [%4];" \
        : "=r"((r)[0]), "=r"((r)[1]), "=r"((r)[2]), "=r"((r)[3]) : "r"(a))

__device__ __forceinline__ void mma_f16(float* c, const uint32_t* a, const uint32_t* b) {
    asm volatile("mma.sync.aligned.m16n8k16.row.col.f32.f16.f16.f32 "
        "{%0,%1,%2,%3}, {%4,%5,%6,%7}, {%8,%9}, {%0,%1,%2,%3};"
        : "+f"(c[0]), "+f"(c[1]), "+f"(c[2]), "+f"(c[3])
        : "r"(a[0]), "r"(a[1]), "r"(a[2]), "r"(a[3]), "r"(b[0]), "r"(b[1]));
}

// ---------------- prep kernels ----------------
__global__ void k_style(const float* __restrict__ style,
                        const float* __restrict__ style_w,
                        const float* __restrict__ style_b) {
    int n = blockIdx.x, ci = threadIdx.x;
    const float* srow = style + n * STY;
    const float* wrow = style_w + ci * STY;
    float acc = 0.f;
    #pragma unroll 8
    for (int j = 0; j < STY; j++) acc += srow[j] * wrow[j];
    g_s[n * CIN + ci] = acc + style_b[ci];
}

// weights -> fp16 [c16][cotile][tap][co128][16ci], halves swapped when co&4
__global__ void k_wprep(const float* __restrict__ weight) {
    int id = blockIdx.x * 256 + threadIdx.x;
    int ci = id & 511, co = id >> 9;
    const float* wp = weight + (size_t)(co * CIN + ci) * 9;
    int c16 = ci >> 4, cil = ci & 15;
    int cotile = co >> 7, col = co & 127;
    int cil_sw = (col & 4) ? (cil ^ 8) : cil;    // bank-conflict swizzle
    float s = 0.f;
    #pragma unroll
    for (int tap = 0; tap < 9; tap++) {
        float v = wp[tap];
        s += v * v;
        g_wB[(((size_t)(c16 * 4 + cotile) * 9 + tap) * 128 + col) * 16 + cil_sw] =
            __float2half_rn(v);
    }
    g_wsq[co * CIN + ci] = s;
}

__global__ void k_demod() {
    int co = blockIdx.x, n = blockIdx.y;
    __shared__ float red[128];
    float acc = 0.f;
    for (int ci = threadIdx.x; ci < CIN; ci += 128) {
        float s = g_s[n * CIN + ci];
        acc += g_wsq[co * CIN + ci] * s * s;
    }
    red[threadIdx.x] = acc;
    __syncthreads();
    for (int st = 64; st > 0; st >>= 1) {
        if (threadIdx.x < st) red[threadIdx.x] += red[threadIdx.x + st];
        __syncthreads();
    }
    if (threadIdx.x == 0) g_demod[n * COUT + co] = rsqrtf(red[0] + EPSV);
}

// x*s -> fp16 [n][c16][p][16], halves swapped when halo-col (w+1)&4
__global__ void k_xmod(const float* __restrict__ x) {
    int b   = blockIdx.x;
    int n   = b >> 9;
    int c16 = (b >> 4) & 31;
    int pb  = b & 15;
    int p   = pb * 256 + threadIdx.x;
    const float* sp = g_s + n * CIN + c16 * 16;
    const float* xp = x + (size_t)(n * CIN + c16 * 16) * HW + p;
    uint32_t hi[8];
    #pragma unroll
    for (int j = 0; j < 8; j++) {
        float v0 = xp[(size_t)(2 * j) * HW]     * sp[2 * j];
        float v1 = xp[(size_t)(2 * j + 1) * HW] * sp[2 * j + 1];
        __half2 hp = __halves2half2(__float2half_rn(v0), __float2half_rn(v1));
        hi[j] = *reinterpret_cast<uint32_t*>(&hp);
    }
    size_t ob = ((size_t)(n * 32 + c16) * HW + p) * 16;
    uint4* oh = reinterpret_cast<uint4*>(g_xm + ob);
    uint4 lo4 = make_uint4(hi[0], hi[1], hi[2], hi[3]);
    uint4 hi4 = make_uint4(hi[4], hi[5], hi[6], hi[7]);
    if (((p & 63) + 1) & 4) {
        oh[0] = hi4; oh[1] = lo4;
    } else {
        oh[0] = lo4; oh[1] = hi4;
    }
}

// ---------------- main HMMA kernel (persistent, 2-stage, swizzled) -----------
#define A_BYTES   12672      // [6][66][16] halfs
#define B_BYTES   36864      // [9][128][16] halfs
#define SSTRIDE   (A_BYTES + B_BYTES)            // 49536
#define SM_DATA   1024
#define SM_EPI    (SM_DATA + 2 * SSTRIDE)        // 100096
#define EPI_STRIDE 2176                          // 8 rows * 68 floats * 4 B
#define SMEM_TOTAL (SM_EPI + 8 * EPI_STRIDE)     // 117504
#define EXPECT_B  (6 * 2048 + B_BYTES)           // 49152

__device__ __forceinline__ void issue_stage(uint32_t sb, int ls, int bx) {
    int tord = ls >> 5, c16 = ls & 31;
    int tile = bx + NCTA * tord;
    int n = tile >> 6, rem = tile & 63;
    int h0 = (rem >> 2) * 4;
    int cotile = rem & 3;
    int slot = ls & 1;
    uint32_t sa = sb + SM_DATA + slot * SSTRIDE;
    uint32_t mb = sb + slot * 8;
    MBAR_EXPECT(mb, EXPECT_B);
    const __half* xbase = g_xm + ((size_t)(n * 32 + c16) * HW) * 16;
    #pragma unroll
    for (int r = 0; r < 6; r++) {
        int hh = h0 - 1 + r;
        const __half* src = ((unsigned)hh < 64u) ? (xbase + (size_t)hh * 64 * 16)
                                                 : g_zero;
        BULK(sa + (r * 66 + 1) * 32, src, 2048, mb);
    }
    BULK(sa + A_BYTES, g_wB + (size_t)(c16 * 4 + cotile) * 18432, B_BYTES, mb);
}

#define LOADB(BH, addr)                                           \
    do {                                                          \
        uint32_t _bb = (addr);                                    \
        uint32_t _bq[4];                                          \
        LDSM4(_bq, _bb);          (BH)[0][0]=_bq[0]; (BH)[0][1]=_bq[1]; (BH)[1][0]=_bq[2]; (BH)[1][1]=_bq[3]; \
        LDSM4(_bq, _bb + 512);    (BH)[2][0]=_bq[0]; (BH)[2][1]=_bq[1]; (BH)[3][0]=_bq[2]; (BH)[3][1]=_bq[3]; \
        LDSM4(_bq, _bb + 1024);   (BH)[4][0]=_bq[0]; (BH)[4][1]=_bq[1]; (BH)[5][0]=_bq[2]; (BH)[5][1]=_bq[3]; \
        LDSM4(_bq, _bb + 1536);   (BH)[6][0]=_bq[0]; (BH)[6][1]=_bq[1]; (BH)[7][0]=_bq[2]; (BH)[7][1]=_bq[3]; \
    } while (0)

// One tap. ROFF = dh*2112 compile-time; AIDX = dw+1 selects per-lane A offset.
// Non-last taps: ALL 8 LDSM (A for this tap + B for next) issue at the tap head,
// burying A-fragment latency under the LDSM issue stream before the first MMA.
#define TAPB(lsv, slotv, tapv, ROFF, AIDX, CUR, NXT, ISLAST)                     \
    do {                                                                         \
        uint32_t _saA = sb + SM_DATA + (slotv) * SSTRIDE;                        \
        uint32_t _aa = _saA + aof[AIDX] + (ROFF);                                \
        uint32_t ah0[4], ah1[4], ah2[4], ah3[4];                                 \
        LDSM4(ah0, _aa);                                                         \
        LDSM4(ah1, _aa + 512);                                                   \
        LDSM4(ah2, _aa + 1024);                                                  \
        LDSM4(ah3, _aa + 1536);                                                  \
        if (!(ISLAST)) {                                                         \
            LOADB(NXT, _saA + A_BYTES + ((tapv) + 1) * 4096 + boff);             \
        }                                                                        \
        if (ISLAST) { if (lane == 0) MBAR_ARRIVE(sb + 64 + (slotv) * 8); }       \
        _Pragma("unroll")                                                        \
        for (int bn = 0; bn < 8; bn++) mma_f16(acc[0][bn], ah0, CUR[bn]);        \
        _Pragma("unroll")                                                        \
        for (int bn = 0; bn < 8; bn++) mma_f16(acc[1][bn], ah1, CUR[bn]);        \
        if ((ISLAST) && (lsv) + 1 < nls) {                                       \
            MBAR_WAIT(sb + (1 - (slotv)) * 8, (((lsv) + 1) >> 1) & 1);           \
            LOADB(NXT, sb + SM_DATA + (1 - (slotv)) * SSTRIDE + A_BYTES + boff); \
        }                                                                        \
        _Pragma("unroll")                                                        \
        for (int bn = 0; bn < 8; bn++) mma_f16(acc[2][bn], ah2, CUR[bn]);        \
        _Pragma("unroll")                                                        \
        for (int bn = 0; bn < 8; bn++) mma_f16(acc[3][bn], ah3, CUR[bn]);        \
        if ((ISLAST) && (lsv) + 2 < nls) {                                       \
            if (wid == ((lsv) & 7) && lane == 0) {                               \
                MBAR_WAIT(sb + 64 + (slotv) * 8, ((lsv) >> 1) & 1);              \
                issue_stage(sb, (lsv) + 2, bx);                                  \
            }                                                                    \
        }                                                                        \
    } while (0)

#define STAGE(lsv, slotv, B0, B1)                          \
    do {                                                   \
        TAPB(lsv, slotv, 0, -2112, 0, B0, B1, 0);          \
        TAPB(lsv, slotv, 1, -2112, 1, B1, B0, 0);          \
        TAPB(lsv, slotv, 2, -2112, 2, B0, B1, 0);          \
        TAPB(lsv, slotv, 3,     0, 0, B1, B0, 0);          \
        TAPB(lsv, slotv, 4,     0, 1, B0, B1, 0);          \
        TAPB(lsv, slotv, 5,     0, 2, B1, B0, 0);          \
        TAPB(lsv, slotv, 6,  2112, 0, B0, B1, 0);          \
        TAPB(lsv, slotv, 7,  2112, 1, B1, B0, 0);          \
        TAPB(lsv, slotv, 8,  2112, 2, B0, B1, 1);          \
    } while (0)

__global__ void __launch_bounds__(256, 1)
k_main(const float* __restrict__ noise,
       const float* __restrict__ nw_p,
       float* __restrict__ out) {
    extern __shared__ __align__(1024) char smem[];
    uint32_t sb = smem_u32(smem);
    int t = threadIdx.x, wid = t >> 5, lane = t & 31;
    int wm = wid & 3, wn = wid >> 2;
    int bx = blockIdx.x;

    int ntiles = (NTILES_TOTAL - bx + NCTA - 1) / NCTA;
    int nls = ntiles * 32;

    if (t == 0) {
        #pragma unroll
        for (int s = 0; s < 2; s++) {
            MBAR_INIT(sb + s * 8, 1);
            MBAR_INIT(sb + 64 + s * 8, 8);
        }
    }
    {
        uint32_t zb = sb + SM_DATA;
        for (int i = t * 16; i < A_BYTES; i += 4096) {
            asm volatile(
                "st.shared.v4.b32 [%0], {%2,%2,%2,%2};\n\t"
                "st.shared.v4.b32 [%1], {%2,%2,%2,%2};"
                :: "r"(zb + i), "r"(zb + SSTRIDE + i), "r"(0u) : "memory");
        }
    }
    __syncthreads();
    if (lane == 0 && wid < 2) {
        FENCE_ASYNC();
        issue_stage(sb, wid, bx);
    }

    float acc[4][8][4];
    #pragma unroll
    for (int a = 0; a < 4; a++)
        #pragma unroll
        for (int b = 0; b < 8; b++)
            #pragma unroll
            for (int c = 0; c < 4; c++) acc[a][b][c] = 0.f;

    // swizzled lane offsets
    int bg = lane >> 3, br = lane & 7;
    uint32_t boff = (uint32_t)((wn * 64 + (bg >> 1) * 8 + br) * 32)
                  + (uint32_t)((((bg & 1) ^ ((br >> 2) & 1)) ) * 16);
    int pxl = lane & 15, hh = lane >> 4;
    uint32_t aof[3];
    #pragma unroll
    for (int d = 0; d < 3; d++) {
        int c = pxl + d;
        aof[d] = (uint32_t)(((wm + 1) * 66 + c) * 32)
               + (uint32_t)((hh ^ ((c >> 2) & 1)) * 16);
    }

    uint32_t bhA[8][2], bhB[8][2];
    float nw = nw_p[0];

    // prologue
    MBAR_WAIT(sb + 0, 0);
    LOADB(bhA, sb + SM_DATA + A_BYTES + boff);

    int tile = bx;
    for (int tord = 0; tord < ntiles; tord++, tile += NCTA) {
        int lsbase = tord * 32;
        for (int cc = 0; cc < 32; cc += 2) {
            STAGE(lsbase + cc,     0, bhA, bhB);
            STAGE(lsbase + cc + 1, 1, bhB, bhA);
        }

        // ---- warp-local epilogue (padded smem, conflict-free stores) ----
        {
            int n   = tile >> 6;
            int rem = tile & 63;
            int p0  = (rem >> 2) * 256;
            int co0 = (rem & 3) * 128;

            int q = lane & 3, rr = lane >> 2;
            int pxbase = p0 + wm * 64 + q * 16;
            float nzs[16];
            #pragma unroll
            for (int j = 0; j < 16; j++) nzs[j] = nw * noise[n * HW + pxbase + j];

            float* wsm = reinterpret_cast<float*>(smem + SM_EPI + wid * EPI_STRIDE);
            const float* dmrow = g_demod + n * COUT;

            #pragma unroll
            for (int g = 0; g < 8; g++) {
                #pragma unroll
                for (int am = 0; am < 4; am++) {
                    int px = am * 16 + (lane >> 2);
                    int col = (lane & 3) * 2;
                    wsm[col * 68 + px]           = acc[am][g][0];
                    wsm[(col + 1) * 68 + px]     = acc[am][g][1];
                    wsm[col * 68 + px + 8]       = acc[am][g][2];
                    wsm[(col + 1) * 68 + px + 8] = acc[am][g][3];
                }
                __syncwarp();
                int co = co0 + wn * 64 + g * 8 + rr;
                float d = dmrow[co];
                float* op = out + ((size_t)(n * COUT + co)) * HW + pxbase;
                const float* srp = wsm + rr * 68 + q * 16;
                #pragma unroll
                for (int j4 = 0; j4 < 4; j4++) {
                    float4 v = *reinterpret_cast<const float4*>(srp + j4 * 4);
                    float r0 = v.x * d + nzs[j4 * 4 + 0];
                    float r1 = v.y * d + nzs[j4 * 4 + 1];
                    float r2 = v.z * d + nzs[j4 * 4 + 2];
                    float r3 = v.w * d + nzs[j4 * 4 + 3];
                    r0 = (r0 >= 0.f) ? r0 : 0.2f * r0;
                    r1 = (r1 >= 0.f) ? r1 : 0.2f * r1;
                    r2 = (r2 >= 0.f) ? r2 : 0.2f * r2;
                    r3 = (r3 >= 0.f) ? r3 : 0.2f * r3;
                    *reinterpret_cast<float4*>(op + j4 * 4) = make_float4(r0, r1, r2, r3);
                }
                __syncwarp();
            }
        }

        #pragma unroll
        for (int a = 0; a < 4; a++)
            #pragma unroll
            for (int b = 0; b < 8; b++)
                #pragma unroll
                for (int c = 0; c < 4; c++) acc[a][b][c] = 0.f;
    }
}

// ---------------------------------------------------------------------------
extern "C" void kernel_launch(void* const* d_in, const int* in_sizes, int n_in,
                              void* d_out, int out_size) {
    const float* x            = (const float*)d_in[0];
    const float* style        = (const float*)d_in[1];
    const float* noise        = (const float*)d_in[2];
    const float* weight       = (const float*)d_in[3];
    const float* style_w      = (const float*)d_in[4];
    const float* style_b      = (const float*)d_in[5];
    const float* noise_weight = (const float*)d_in[6];
    float* out = (float*)d_out;

    static cudaStream_t s1 = nullptr;
    static cudaEvent_t eFork = nullptr, eStyle = nullptr, eSide = nullptr;
    if (!s1) {
        cudaStreamCreateWithFlags(&s1, cudaStreamNonBlocking);
        cudaEventCreateWithFlags(&eFork,  cudaEventDisableTiming);
        cudaEventCreateWithFlags(&eStyle, cudaEventDisableTiming);
        cudaEventCreateWithFlags(&eSide,  cudaEventDisableTiming);
        cudaFuncSetAttribute(k_main, cudaFuncAttributeMaxDynamicSharedMemorySize,
                             SMEM_TOTAL);
    }

    // fork: s1 runs wprep (independent) then demod (needs style + wprep)
    cudaEventRecord(eFork, 0);
    cudaStreamWaitEvent(s1, eFork, 0);
    k_wprep<<<1024, 256, 0, s1>>>(weight);

    k_style<<<NB, CIN>>>(style, style_w, style_b);
    cudaEventRecord(eStyle, 0);
    cudaStreamWaitEvent(s1, eStyle, 0);
    {
        dim3 g(COUT, NB);
        k_demod<<<g, 128, 0, s1>>>();
    }
    cudaEventRecord(eSide, s1);

    k_xmod<<<8192, 256>>>(x);              // main stream, after style
    cudaStreamWaitEvent(0, eSide, 0);      // join before k_main
    k_main<<<NCTA, 256, SMEM_TOTAL>>>(noise, noise_weight, out);
}